// round 6
// baseline (speedup 1.0000x reference)
#include <cuda_runtime.h>
#include <cstdint>

#define BB   2048
#define TT   256
#define HIDN 256
#define FDIM 70
#define FPAD 80
#define KTOT 336      // 80 (padded feat) + 256 (hidden)
#define MT   128
#define NT   128
#define KT   16

typedef unsigned long long ull;

// Scratch (device globals: allocation-free contract)
__device__ float g_feat[(size_t)TT * FPAD * BB];   // [t][k][b], k>=70 zero-padded
__device__ float g_h[2][HIDN * BB];                // [j][b], double-buffered
__device__ float g_c[HIDN * BB];                   // [j][b]

// ---------------------------------------------------------------------------
// Featurize: conv(2x2, 2->4ch, 5x5 'VALID') + ReLU + one-hot/reward/done
// Writes g_feat[t][k][b] (b contiguous -> coalesced stores).
// ---------------------------------------------------------------------------
__global__ void featurize_kernel(const float* __restrict__ x,
                                 const int*   __restrict__ prev_action,
                                 const float* __restrict__ prev_reward,
                                 const float* __restrict__ prev_done,
                                 const float* __restrict__ conv_w,
                                 const float* __restrict__ conv_b) {
    int idx = blockIdx.x * blockDim.x + threadIdx.x;   // t*BB + b
    int t = idx >> 11;
    int b = idx & (BB - 1);

    const float* xp = x + ((size_t)b * TT + t) * 50;   // (5,5,2) block
    float xv[50];
#pragma unroll
    for (int i = 0; i < 50; i++) xv[i] = xp[i];
    float cw[32];
#pragma unroll
    for (int i = 0; i < 32; i++) cw[i] = conv_w[i];
    float cb[4];
#pragma unroll
    for (int i = 0; i < 4; i++) cb[i] = conv_b[i];

    float* fp = g_feat + (size_t)t * FPAD * BB + b;

#pragma unroll
    for (int c = 0; c < 4; c++)
#pragma unroll
        for (int h = 0; h < 4; h++)
#pragma unroll
            for (int w = 0; w < 4; w++) {
                float s = cb[c];
#pragma unroll
                for (int i = 0; i < 2; i++)
#pragma unroll
                    for (int kh = 0; kh < 2; kh++)
#pragma unroll
                        for (int kw = 0; kw < 2; kw++)
                            s += xv[((h + kh) * 5 + (w + kw)) * 2 + i] *
                                 cw[((c * 2 + i) * 2 + kh) * 2 + kw];
                fp[(size_t)(c * 16 + h * 4 + w) * BB] = fmaxf(s, 0.0f);
            }

    int a = prev_action[(size_t)b * TT + t];
#pragma unroll
    for (int k = 0; k < 4; k++)
        fp[(size_t)(64 + k) * BB] = (a == k) ? 1.0f : 0.0f;
    fp[(size_t)68 * BB] = prev_reward[(size_t)b * TT + t];
    fp[(size_t)69 * BB] = prev_done[(size_t)b * TT + t];
#pragma unroll
    for (int k = FDIM; k < FPAD; k++)
        fp[(size_t)k * BB] = 0.0f;
}

// ---------------------------------------------------------------------------
// Init: hidden (B, 2*HID) row-major -> g_h[0]/g_c in [j][b] layout
// ---------------------------------------------------------------------------
__global__ void init_state_kernel(const float* __restrict__ hidden) {
    int idx = blockIdx.x * blockDim.x + threadIdx.x;   // b*HIDN + j
    int b = idx >> 8;
    int j = idx & 255;
    g_h[0][j * BB + b] = hidden[(size_t)b * 512 + j];
    g_c[j * BB + b]    = hidden[(size_t)b * 512 + 256 + j];
}

// ---------------------------------------------------------------------------
// One LSTM step. Grid (16, 8): blockIdx.x = 128-batch tile, blockIdx.y = 32-j
// tile (NT = 128 gate columns interleaved n_local = j_local*4 + gate).
// gates = feat_t @ w_ih^T + h @ w_hh^T + (b_ih + b_hh), fused pointwise update.
// f32x2 packed FMA (FFMA2); K-loop software-pipelined via register prefetch
// (occ=1 -> no co-resident warps to hide LDG latency otherwise).
// ---------------------------------------------------------------------------
__global__ __launch_bounds__(256, 1)
void lstm_step_kernel(const float* __restrict__ w_ih,
                      const float* __restrict__ w_hh,
                      const float* __restrict__ b_ih,
                      const float* __restrict__ b_hh,
                      float* __restrict__ out, int t, int pin) {
    // SMEM: GEMM buffers aliased with h staging (disjoint lifetimes)
    __shared__ __align__(16) float smem_mm[MT * 33];           // >= KT*MT + KT*(NT+2)
    __shared__ float cs[MT][33];
    float (*As)[MT]     = (float (*)[MT])smem_mm;              // [KT][MT]
    float (*Bs)[NT + 2] = (float (*)[NT + 2])(smem_mm + KT * MT);  // [KT][130]
    float (*hs)[33]     = (float (*)[33])smem_mm;              // [MT][33] (epilogue)

    const int tid = threadIdx.x;
    const int tx  = tid & 15;     // n-direction (16 threads x 8 cols)
    const int ty  = tid >> 4;     // m-direction (16 threads x 8 rows)
    const int m0  = blockIdx.x * MT;
    const int j0  = blockIdx.y * 32;

    // Accumulators (float2 pairs over n), initialized with fused biases
    ull acc[8][4];
    {
        float bv[8];
#pragma unroll
        for (int q = 0; q < 8; q++) {
            int nl = tx * 8 + q;
            int gate = nl & 3, jl = nl >> 2;
            int ng = gate * HIDN + j0 + jl;
            bv[q] = b_ih[ng] + b_hh[ng];
        }
#pragma unroll
        for (int p = 0; p < 4; p++) {
            ull bp;
            asm("mov.b64 %0, {%1, %2};" : "=l"(bp)
                : "r"(__float_as_uint(bv[2 * p])), "r"(__float_as_uint(bv[2 * p + 1])));
#pragma unroll
            for (int mi = 0; mi < 8; mi++) acc[mi][p] = bp;
        }
    }

    const float* hin = g_h[pin];
    const int a_m = tid & 127;
    float aregs[8], bregs[8];

    // Prefetch helper (tile at K0): A from feat or hidden, B weights -> registers
#define LOAD_TILE(K0)                                                          \
    {                                                                          \
        const float* Aptr = ((K0) < FPAD)                                      \
            ? (g_feat + ((size_t)t * FPAD + (K0)) * BB + m0)                   \
            : (hin + (size_t)((K0) - FPAD) * BB + m0);                         \
        _Pragma("unroll")                                                      \
        for (int i = 0; i < 8; i++) {                                          \
            int idx = i * 256 + tid;                                           \
            int kk = (idx >> 7) & 15;                                          \
            aregs[i] = Aptr[(size_t)kk * BB + a_m];                            \
        }                                                                      \
        _Pragma("unroll")                                                      \
        for (int i = 0; i < 8; i++) {                                          \
            int idx = i * 256 + tid;                                           \
            int kk = idx & 15, nl = (idx >> 4) & 127;                          \
            int gate = nl & 3, jl = nl >> 2;                                   \
            int ng = gate * HIDN + j0 + jl;                                    \
            int kg = (K0) + kk;                                                \
            if ((K0) < FPAD) bregs[i] = (kg < FDIM) ? w_ih[ng * FDIM + kg] : 0.0f; \
            else             bregs[i] = w_hh[ng * HIDN + (kg - FPAD)];         \
        }                                                                      \
    }

    LOAD_TILE(0);

    for (int k0 = 0; k0 < KTOT; k0 += KT) {
        // Commit prefetched tile to SMEM
#pragma unroll
        for (int i = 0; i < 8; i++) {
            int idx = i * 256 + tid;
            As[(idx >> 7) & 15][a_m] = aregs[i];
        }
#pragma unroll
        for (int i = 0; i < 8; i++) {
            int idx = i * 256 + tid;
            Bs[idx & 15][(idx >> 4) & 127] = bregs[i];
        }
        __syncthreads();

        // Issue next tile's LDGs now; they drain during the FFMA2 stream below
        if (k0 + KT < KTOT) LOAD_TILE(k0 + KT);

#pragma unroll
        for (int kk = 0; kk < KT; kk++) {
            float4 a0 = *(const float4*)&As[kk][ty * 8];
            float4 a1 = *(const float4*)&As[kk][ty * 8 + 4];
            ull bp[4];
#pragma unroll
            for (int p = 0; p < 4; p++)
                bp[p] = *(const ull*)&Bs[kk][tx * 8 + 2 * p];
            float am[8] = {a0.x, a0.y, a0.z, a0.w, a1.x, a1.y, a1.z, a1.w};
#pragma unroll
            for (int mi = 0; mi < 8; mi++) {
                ull ad;
                asm("mov.b64 %0, {%1, %1};" : "=l"(ad) : "r"(__float_as_uint(am[mi])));
#pragma unroll
                for (int p = 0; p < 4; p++)
                    asm("fma.rn.f32x2 %0, %1, %2, %0;"
                        : "+l"(acc[mi][p]) : "l"(ad), "l"(bp[p]));
            }
        }
        __syncthreads();
    }
#undef LOAD_TILE

    // Load c (coalesced) into SMEM
#pragma unroll
    for (int i = 0; i < 16; i++) {
        int ii = i * 256 + tid;
        int jl = ii >> 7, m = ii & 127;
        cs[m][jl] = g_c[(size_t)(j0 + jl) * BB + m0 + m];
    }
    __syncthreads();

    // Pointwise LSTM update; each thread owns full (i,f,g,o) quadruples
#pragma unroll
    for (int mi = 0; mi < 8; mi++) {
        int mrow = ty * 8 + mi;
#pragma unroll
        for (int jj = 0; jj < 2; jj++) {
            int jl = tx * 2 + jj;
            float gi, gf, gg, go;
            { ull u = acc[mi][jj * 2];
              gi = __uint_as_float((unsigned)u);
              gf = __uint_as_float((unsigned)(u >> 32)); }
            { ull u = acc[mi][jj * 2 + 1];
              gg = __uint_as_float((unsigned)u);
              go = __uint_as_float((unsigned)(u >> 32)); }
            float cprev = cs[mrow][jl];
            float si = 1.0f / (1.0f + __expf(-gi));
            float sf = 1.0f / (1.0f + __expf(-gf));
            float so = 1.0f / (1.0f + __expf(-go));
            float cn = sf * cprev + si * tanhf(gg);
            float hn = so * tanhf(cn);
            cs[mrow][jl] = cn;   // owned exclusively by this thread
            hs[mrow][jl] = hn;
        }
    }
    __syncthreads();

    // Write back h (next buffer) and c, coalesced over b
    float* hout = g_h[pin ^ 1];
#pragma unroll
    for (int i = 0; i < 16; i++) {
        int ii = i * 256 + tid;
        int jl = ii >> 7, m = ii & 127;
        hout[(size_t)(j0 + jl) * BB + m0 + m] = hs[m][jl];
        g_c [(size_t)(j0 + jl) * BB + m0 + m] = cs[m][jl];
    }
    // Features out: (B, T, HID) row-major, 128B contiguous per (b,t)
    int lane = tid & 31;
#pragma unroll
    for (int r = tid >> 5; r < MT; r += 8)
        out[((size_t)(m0 + r) * TT + t) * HIDN + j0 + lane] = hs[r][lane];
}

// ---------------------------------------------------------------------------
// Final hidden_out = concat(h, c) in (B, 2*HID) row-major
// ---------------------------------------------------------------------------
__global__ void write_hidden_kernel(float* __restrict__ out, int pfin) {
    int idx = blockIdx.x * blockDim.x + threadIdx.x;   // b*512 + col
    int b = idx >> 9;
    int col = idx & 511;
    float v = (col < HIDN) ? g_h[pfin][col * BB + b]
                           : g_c[(col - HIDN) * BB + b];
    out[idx] = v;
}

// ---------------------------------------------------------------------------
extern "C" void kernel_launch(void* const* d_in, const int* in_sizes, int n_in,
                              void* d_out, int out_size) {
    const float* x           = (const float*)d_in[0];
    const float* hidden      = (const float*)d_in[1];
    const int*   prev_action = (const int*)  d_in[2];
    const float* prev_reward = (const float*)d_in[3];
    const float* prev_done   = (const float*)d_in[4];
    const float* conv_w      = (const float*)d_in[5];
    const float* conv_b      = (const float*)d_in[6];
    const float* w_ih        = (const float*)d_in[7];
    const float* w_hh        = (const float*)d_in[8];
    const float* b_ih        = (const float*)d_in[9];
    const float* b_hh        = (const float*)d_in[10];
    float* out = (float*)d_out;

    featurize_kernel<<<(BB * TT) / 256, 256>>>(x, prev_action, prev_reward,
                                               prev_done, conv_w, conv_b);
    init_state_kernel<<<(BB * HIDN) / 256, 256>>>(hidden);

    dim3 grid(BB / MT, HIDN / 32);
    for (int t = 0; t < TT; t++)
        lstm_step_kernel<<<grid, 256>>>(w_ih, w_hh, b_ih, b_hh, out, t, t & 1);

    write_hidden_kernel<<<(BB * 2 * HIDN) / 256, 256>>>(
        out + (size_t)BB * TT * HIDN, TT & 1);
}

// round 13
// speedup vs baseline: 2.2948x; 2.2948x over previous
#include <cuda_runtime.h>
#include <cuda_bf16.h>
#include <cstdint>

#define BB    2048
#define TT    256
#define HIDN  256
#define NG    1024          // 4*HIDN gate columns (permuted n' = 4j+gate)
#define KFEAT 128           // 70 real feature dims, zero-padded
#define NCHUNK 6            // 2 feat chunks + 4 hidden chunks, 64 bf16 each

// ---------------- device scratch (module-load allocated) -------------------
__device__ __align__(256) __nv_bfloat16 g_feat_hi[(size_t)BB * TT * KFEAT];
__device__ __align__(256) __nv_bfloat16 g_feat_lo[(size_t)BB * TT * KFEAT];
__device__ __align__(256) __nv_bfloat16 g_h_hi[2][(size_t)BB * HIDN];
__device__ __align__(256) __nv_bfloat16 g_h_lo[2][(size_t)BB * HIDN];
__device__ __align__(256) float         g_c[(size_t)BB * HIDN];
__device__ __align__(256) __nv_bfloat16 g_wih_hi[NG * KFEAT], g_wih_lo[NG * KFEAT];
__device__ __align__(256) __nv_bfloat16 g_whh_hi[NG * HIDN],  g_whh_lo[NG * HIDN];
__device__ __align__(256) float         g_bias[NG];

// ---------------- helpers (family-portable PTX only) -----------------------
__device__ __forceinline__ uint32_t smem_u32(const void* p) {
    uint32_t a;
    asm("{ .reg .u64 t; cvta.to.shared.u64 t, %1; cvt.u32.u64 %0, t; }" : "=r"(a) : "l"(p));
    return a;
}
__device__ __forceinline__ uint32_t lds32(uint32_t a) {
    uint32_t v;
    asm volatile("ld.shared.b32 %0, [%1];" : "=r"(v) : "r"(a));
    return v;
}
#define CP_ASYNC16(dst, src) \
    asm volatile("cp.async.ca.shared.global [%0], [%1], 16;" :: "r"(dst), "l"(src) : "memory")
#define CP_COMMIT() asm volatile("cp.async.commit_group;" ::: "memory")
#define CP_WAIT(n)  asm volatile("cp.async.wait_group %0;" :: "n"(n) : "memory")

// m16n8k16 bf16 MMA, f32 accumulate (standard PTX, sm_80+, family-portable)
#define MMA16816(D, A, B) \
    asm volatile("mma.sync.aligned.m16n8k16.row.col.f32.bf16.bf16.f32 " \
        "{%0,%1,%2,%3}, {%4,%5,%6,%7}, {%8,%9}, {%0,%1,%2,%3};" \
        : "+f"((D)[0]), "+f"((D)[1]), "+f"((D)[2]), "+f"((D)[3]) \
        : "r"((A)[0]), "r"((A)[1]), "r"((A)[2]), "r"((A)[3]), \
          "r"((B)[0]), "r"((B)[1]))

__device__ __forceinline__ void split_bf16(float v, __nv_bfloat16& hi, __nv_bfloat16& lo) {
    hi = __float2bfloat16(v);
    lo = __float2bfloat16(v - __bfloat162float(hi));
}

// ---------------------------------------------------------------------------
// Featurize: conv(2x2,2->4) + ReLU + one-hot/reward/done -> bf16 hi/lo rows
// ---------------------------------------------------------------------------
__global__ void featurize_kernel(const float* __restrict__ x,
                                 const int*   __restrict__ prev_action,
                                 const float* __restrict__ prev_reward,
                                 const float* __restrict__ prev_done,
                                 const float* __restrict__ conv_w,
                                 const float* __restrict__ conv_b) {
    int g = blockIdx.x * blockDim.x + threadIdx.x;
    int t = g >> 11, b = g & (BB - 1);

    const float* xp = x + ((size_t)b * TT + t) * 50;
    float xv[50];
#pragma unroll
    for (int i = 0; i < 50; i++) xv[i] = xp[i];
    float cw[32];
#pragma unroll
    for (int i = 0; i < 32; i++) cw[i] = conv_w[i];
    float cb[4];
#pragma unroll
    for (int i = 0; i < 4; i++) cb[i] = conv_b[i];

    float v[70];
#pragma unroll
    for (int c = 0; c < 4; c++)
#pragma unroll
        for (int h = 0; h < 4; h++)
#pragma unroll
            for (int w = 0; w < 4; w++) {
                float s = cb[c];
#pragma unroll
                for (int i = 0; i < 2; i++)
#pragma unroll
                    for (int kh = 0; kh < 2; kh++)
#pragma unroll
                        for (int kw = 0; kw < 2; kw++)
                            s += xv[((h + kh) * 5 + (w + kw)) * 2 + i] *
                                 cw[((c * 2 + i) * 2 + kh) * 2 + kw];
                v[c * 16 + h * 4 + w] = fmaxf(s, 0.0f);
            }
    int a = prev_action[(size_t)b * TT + t];
#pragma unroll
    for (int k = 0; k < 4; k++) v[64 + k] = (a == k) ? 1.0f : 0.0f;
    v[68] = prev_reward[(size_t)b * TT + t];
    v[69] = prev_done[(size_t)b * TT + t];

    __nv_bfloat16* ph = g_feat_hi + (size_t)g * KFEAT;
    __nv_bfloat16* pl = g_feat_lo + (size_t)g * KFEAT;
#pragma unroll
    for (int k = 0; k < 70; k++) { __nv_bfloat16 h_, l_; split_bf16(v[k], h_, l_); ph[k] = h_; pl[k] = l_; }
#pragma unroll
    for (int k = 70; k < KFEAT; k++) { ph[k] = __float2bfloat16(0.f); pl[k] = __float2bfloat16(0.f); }
}

// ---------------------------------------------------------------------------
// One-time weight conversion: permuted rows n' = 4*j + gate (src n = gate*256+j)
// ---------------------------------------------------------------------------
__global__ void convert_weights_kernel(const float* __restrict__ w_ih,
                                       const float* __restrict__ w_hh,
                                       const float* __restrict__ b_ih,
                                       const float* __restrict__ b_hh) {
    int idx = blockIdx.x * blockDim.x + threadIdx.x;   // up to NG*HIDN
    {   // w_hh: [1024][256]
        int np = idx >> 8, k = idx & 255;
        int n = (np & 3) * HIDN + (np >> 2);
        __nv_bfloat16 h_, l_;
        split_bf16(w_hh[n * HIDN + k], h_, l_);
        g_whh_hi[np * HIDN + k] = h_;
        g_whh_lo[np * HIDN + k] = l_;
    }
    if (idx < NG * KFEAT) {   // w_ih padded 70 -> 128
        int np = idx >> 7, k = idx & 127;
        int n = (np & 3) * HIDN + (np >> 2);
        float v = (k < 70) ? w_ih[n * 70 + k] : 0.0f;
        __nv_bfloat16 h_, l_;
        split_bf16(v, h_, l_);
        g_wih_hi[np * KFEAT + k] = h_;
        g_wih_lo[np * KFEAT + k] = l_;
    }
    if (idx < NG) {
        int n = (idx & 3) * HIDN + (idx >> 2);
        g_bias[idx] = b_ih[n] + b_hh[n];
    }
}

// ---------------------------------------------------------------------------
// Init state: h -> bf16 hi/lo, c -> fp32, layout [b][j]
// ---------------------------------------------------------------------------
__global__ void init_state_kernel(const float* __restrict__ hidden) {
    int idx = blockIdx.x * blockDim.x + threadIdx.x;   // b*256 + j
    int b = idx >> 8, j = idx & 255;
    __nv_bfloat16 h_, l_;
    split_bf16(hidden[(size_t)b * 512 + j], h_, l_);
    g_h_hi[0][idx] = h_;
    g_h_lo[0][idx] = l_;
    g_c[idx] = hidden[(size_t)b * 512 + 256 + j];
}

// ---------------------------------------------------------------------------
// LSTM step: warp-level bf16 MMA (m16n8k16), 3-term hi/lo split, cp.async
// double-buffered K-chunks, fused gate epilogue.
// grid (16,8): 128 batch rows x 128 gate cols per CTA; 256 threads (8 warps).
// ---------------------------------------------------------------------------
#define ROWP   72                       // padded row length in bf16 (144 B)
#define TILE_B (128 * ROWP * 2)         // 18432 B per operand tile
#define STAGE_B (4 * TILE_B)            // Ahi, Alo, Bhi, Blo = 73728 B
#define SM_TOTAL (2 * STAGE_B)          // double buffered = 147456 B

__device__ __forceinline__ void cpa_tile(uint32_t dst_base,
                                         const __nv_bfloat16* src, int stride,
                                         int tid) {
#pragma unroll
    for (int i = 0; i < 4; i++) {
        int idx = i * 256 + tid;
        int row = idx >> 3, c8 = idx & 7;
        uint32_t dst = dst_base + row * (ROWP * 2) + c8 * 16;
        CP_ASYNC16(dst, src + (size_t)row * stride + c8 * 8);
    }
}

__global__ __launch_bounds__(256, 1)
void lstm_mma_step(float* __restrict__ out, int t, int pin) {
    extern __shared__ char smem[];
    uint32_t sb = smem_u32(smem);
    const int tid = threadIdx.x, wid = tid >> 5, lane = tid & 31;
    const int g = lane >> 2, tq = lane & 3;
    const int wm = wid & 1, wn = wid >> 1;      // 2 x 4 warp grid (64x32 tiles)
    const int m0 = blockIdx.x * 128;
    const int nt = blockIdx.y;                  // gate-col tile (128 n' = 32 j)
    const int pout = pin ^ 1;

    float acc[4][4][4];
#pragma unroll
    for (int a = 0; a < 4; a++)
#pragma unroll
        for (int b = 0; b < 4; b++)
#pragma unroll
            for (int c = 0; c < 4; c++) acc[a][b][c] = 0.0f;

    const __nv_bfloat16* hhi = g_h_hi[pin];
    const __nv_bfloat16* hlo = g_h_lo[pin];

    // stage loader: chunk ck (0-1 = feat K-halves, 2-5 = hidden K-quarters)
#define LOAD_STAGE(CK, BUF)                                                    \
    {                                                                          \
        uint32_t s0 = sb + (BUF) * STAGE_B;                                    \
        if ((CK) < 2) {                                                        \
            size_t ao = ((size_t)(t * BB + m0)) * KFEAT + (CK) * 64;           \
            size_t bo = ((size_t)(nt * 128)) * KFEAT + (CK) * 64;              \
            cpa_tile(s0,              g_feat_hi + ao, KFEAT, tid);             \
            cpa_tile(s0 + TILE_B,     g_feat_lo + ao, KFEAT, tid);             \
            cpa_tile(s0 + 2 * TILE_B, g_wih_hi  + bo, KFEAT, tid);             \
            cpa_tile(s0 + 3 * TILE_B, g_wih_lo  + bo, KFEAT, tid);             \
        } else {                                                               \
            size_t ao = (size_t)m0 * HIDN + ((CK) - 2) * 64;                   \
            size_t bo = (size_t)(nt * 128) * HIDN + ((CK) - 2) * 64;           \
            cpa_tile(s0,              hhi      + ao, HIDN, tid);               \
            cpa_tile(s0 + TILE_B,     hlo      + ao, HIDN, tid);               \
            cpa_tile(s0 + 2 * TILE_B, g_whh_hi + bo, HIDN, tid);               \
            cpa_tile(s0 + 3 * TILE_B, g_whh_lo + bo, HIDN, tid);               \
        }                                                                      \
    }

    LOAD_STAGE(0, 0);
    CP_COMMIT();

#pragma unroll
    for (int ck = 0; ck < NCHUNK; ck++) {
        if (ck + 1 < NCHUNK) { LOAD_STAGE(ck + 1, (ck + 1) & 1); CP_COMMIT(); }
        if (ck + 1 < NCHUNK) CP_WAIT(1); else CP_WAIT(0);
        __syncthreads();

        uint32_t st  = sb + (ck & 1) * STAGE_B;
        uint32_t aH = st, aL = st + TILE_B, bH = st + 2 * TILE_B, bL = st + 3 * TILE_B;

#pragma unroll
        for (int ks = 0; ks < 4; ks++) {
            int kb = ks * 32 + 4 * tq;          // byte offset of col 2t
            uint32_t ahi[4][4], alo[4][4], bhi[4][2], blo[4][2];
#pragma unroll
            for (int mi = 0; mi < 4; mi++) {
                uint32_t r0 = (uint32_t)(wm * 64 + mi * 16 + g) * (ROWP * 2) + kb;
                ahi[mi][0] = lds32(aH + r0);
                ahi[mi][1] = lds32(aH + r0 + 8 * (ROWP * 2));
                ahi[mi][2] = lds32(aH + r0 + 16);
                ahi[mi][3] = lds32(aH + r0 + 8 * (ROWP * 2) + 16);
                alo[mi][0] = lds32(aL + r0);
                alo[mi][1] = lds32(aL + r0 + 8 * (ROWP * 2));
                alo[mi][2] = lds32(aL + r0 + 16);
                alo[mi][3] = lds32(aL + r0 + 8 * (ROWP * 2) + 16);
            }
#pragma unroll
            for (int ni = 0; ni < 4; ni++) {
                uint32_t rb = (uint32_t)(wn * 32 + ni * 8 + g) * (ROWP * 2) + kb;
                bhi[ni][0] = lds32(bH + rb);
                bhi[ni][1] = lds32(bH + rb + 16);
                blo[ni][0] = lds32(bL + rb);
                blo[ni][1] = lds32(bL + rb + 16);
            }
#pragma unroll
            for (int mi = 0; mi < 4; mi++)
#pragma unroll
                for (int ni = 0; ni < 4; ni++) {
                    MMA16816(acc[mi][ni], ahi[mi], bhi[ni]);
                    MMA16816(acc[mi][ni], ahi[mi], blo[ni]);
                    MMA16816(acc[mi][ni], alo[mi], bhi[ni]);
                }
        }
        __syncthreads();
    }
#undef LOAD_STAGE

    // ---- stage gates to SMEM (f32, padded 132-word rows, aliases stage 0)
    float (*sg)[132] = (float (*)[132])(smem);
#pragma unroll
    for (int mi = 0; mi < 4; mi++)
#pragma unroll
        for (int ni = 0; ni < 4; ni++) {
            int r0 = wm * 64 + mi * 16 + g;
            int c0 = wn * 32 + ni * 8 + 2 * tq;
            *(float2*)&sg[r0][c0]     = make_float2(acc[mi][ni][0], acc[mi][ni][1]);
            *(float2*)&sg[r0 + 8][c0] = make_float2(acc[mi][ni][2], acc[mi][ni][3]);
        }
    __syncthreads();

    // ---- fused LSTM pointwise update, fully coalesced global I/O
    __nv_bfloat16* ohi = g_h_hi[pout];
    __nv_bfloat16* olo = g_h_lo[pout];
#pragma unroll
    for (int i = 0; i < 16; i++) {
        int idx = i * 256 + tid;
        int r = idx >> 5, jl = idx & 31;
        float4 gv = *(float4*)&sg[r][4 * jl];
        float4 bv = *(const float4*)(g_bias + 4 * (nt * 32 + jl));
        size_t ga = (size_t)(m0 + r) * HIDN + nt * 32 + jl;
        float cp = g_c[ga];
        float gi = gv.x + bv.x, gf = gv.y + bv.y;
        float gg = gv.z + bv.z, go = gv.w + bv.w;
        float si = 1.0f / (1.0f + __expf(-gi));
        float sf = 1.0f / (1.0f + __expf(-gf));
        float so = 1.0f / (1.0f + __expf(-go));
        float cn = sf * cp + si * tanhf(gg);
        float hn = so * tanhf(cn);
        g_c[ga] = cn;
        __nv_bfloat16 h_, l_;
        split_bf16(hn, h_, l_);
        ohi[ga] = h_;
        olo[ga] = l_;
        out[((size_t)(m0 + r) * TT + t) * HIDN + nt * 32 + jl] = hn;
    }
}

// ---------------------------------------------------------------------------
// hidden_out = concat(h_final, c); h_final read from features[:, T-1]
// ---------------------------------------------------------------------------
__global__ void write_hidden_kernel(const float* __restrict__ feat_out,
                                    float* __restrict__ out2) {
    int idx = blockIdx.x * blockDim.x + threadIdx.x;   // b*512 + col
    int b = idx >> 9, col = idx & 511;
    float v = (col < HIDN)
        ? feat_out[((size_t)b * TT + (TT - 1)) * HIDN + col]
        : g_c[(size_t)b * HIDN + (col - HIDN)];
    out2[idx] = v;
}

// ---------------------------------------------------------------------------
extern "C" void kernel_launch(void* const* d_in, const int* in_sizes, int n_in,
                              void* d_out, int out_size) {
    const float* x           = (const float*)d_in[0];
    const float* hidden      = (const float*)d_in[1];
    const int*   prev_action = (const int*)  d_in[2];
    const float* prev_reward = (const float*)d_in[3];
    const float* prev_done   = (const float*)d_in[4];
    const float* conv_w      = (const float*)d_in[5];
    const float* conv_b      = (const float*)d_in[6];
    const float* w_ih        = (const float*)d_in[7];
    const float* w_hh        = (const float*)d_in[8];
    const float* b_ih        = (const float*)d_in[9];
    const float* b_hh        = (const float*)d_in[10];
    float* out = (float*)d_out;

    cudaFuncSetAttribute(lstm_mma_step,
                         cudaFuncAttributeMaxDynamicSharedMemorySize, SM_TOTAL);

    featurize_kernel<<<(BB * TT) / 256, 256>>>(x, prev_action, prev_reward,
                                               prev_done, conv_w, conv_b);
    convert_weights_kernel<<<(NG * HIDN) / 256, 256>>>(w_ih, w_hh, b_ih, b_hh);
    init_state_kernel<<<(BB * HIDN) / 256, 256>>>(hidden);

    dim3 grid(BB / 128, NG / 128);
    for (int t = 0; t < TT; t++)
        lstm_mma_step<<<grid, 256, SM_TOTAL>>>(out, t, t & 1);

    write_hidden_kernel<<<(BB * 2 * HIDN) / 256, 256>>>(
        out, out + (size_t)BB * TT * HIDN);
}